// round 7
// baseline (speedup 1.0000x reference)
#include <cuda_runtime.h>
#include <cuda_bf16.h>
#include <stdint.h>

#define N_HALF 4096
#define N_TOT  8192
#define DIM    512
#define TILE   128
#define NCHUNK 8
#define GRID_T 64
#define NUM_TILES 2080
#define NWORKERS 296

__device__ __nv_bfloat16 g_hi[(size_t)N_TOT * DIM];
__device__ float g_sq[N_TOT];
__device__ float g_colsum[DIM];
__device__ float g_coef;
__device__ float g_partials[NUM_TILES];
__device__ int g_tile_ctr;

__device__ __forceinline__ uint32_t smem_u32_of(const void* p) {
    uint32_t a;
    asm("{ .reg .u64 t; cvta.to.shared.u64 t, %1; cvt.u32.u64 %0, t; }" : "=r"(a) : "l"(p));
    return a;
}

#define LDSM_X4(r, addr)                                                       \
    asm volatile("ldmatrix.sync.aligned.m8n8.x4.shared.b16 {%0,%1,%2,%3}, [%4];" \
        : "=r"((r)[0]), "=r"((r)[1]), "=r"((r)[2]), "=r"((r)[3]) : "r"(addr))

#define MMA_BF16(c, a, b0, b1)                                                 \
    asm volatile("mma.sync.aligned.m16n8k16.row.col.f32.bf16.bf16.f32 "        \
        "{%0,%1,%2,%3},{%4,%5,%6,%7},{%8,%9},{%0,%1,%2,%3};"                   \
        : "+f"((c)[0]), "+f"((c)[1]), "+f"((c)[2]), "+f"((c)[3])               \
        : "r"((a)[0]), "r"((a)[1]), "r"((a)[2]), "r"((a)[3]), "r"(b0), "r"(b1))

// ---------------- smem map (bytes) ----------------
// per stage: Ahi (16K) | Bhi (16K) = 32K; 3 stages; 2 CTAs/SM
#define SM_TILE    16384
#define SM_STAGE   32768
#define SM_SQA     98304
#define SM_SQB     (SM_SQA + 512)
#define SM_RED     (SM_SQB + 512)
#define SM_CTRL    (SM_RED + 128)
#define SMEM_TOTAL (SM_CTRL + 16)

// ---------------- preprocess: round to bf16, norms/colsums of ROUNDED data ----
__global__ void zero_colsum_kernel() {
    int i = blockIdx.x * blockDim.x + threadIdx.x;
    if (i < DIM) g_colsum[i] = 0.f;
    if (i == 0) g_tile_ctr = 0;
}

__global__ __launch_bounds__(256) void prep_kernel(const float* __restrict__ src,
                                                   const float* __restrict__ tgt) {
    __shared__ float cs[DIM];
    int tid = threadIdx.x;
    for (int i = tid; i < DIM; i += 256) cs[i] = 0.f;
    __syncthreads();
    int warp = tid >> 5, lane = tid & 31;
    int row = blockIdx.x * 8 + warp;
    const float* p = (row < N_HALF) ? src + (size_t)row * DIM
                                    : tgt + (size_t)(row - N_HALF) * DIM;
    const float2* p2 = (const float2*)p;
    __nv_bfloat162* h2p = (__nv_bfloat162*)(g_hi + (size_t)row * DIM);
    float sq = 0.f;
#pragma unroll
    for (int i = 0; i < 8; i++) {
        int c = lane + 32 * i;
        float2 v = p2[c];
        __nv_bfloat16 hx = __float2bfloat16(v.x);
        __nv_bfloat16 hy = __float2bfloat16(v.y);
        float fx = __bfloat162float(hx);
        float fy = __bfloat162float(hy);
        sq += fx * fx + fy * fy;
        atomicAdd(&cs[2 * c], fx);
        atomicAdd(&cs[2 * c + 1], fy);
        __nv_bfloat162 h2; h2.x = hx; h2.y = hy;
        h2p[c] = h2;
    }
#pragma unroll
    for (int o = 16; o; o >>= 1) sq += __shfl_xor_sync(0xffffffffu, sq, o);
    if (lane == 0) g_sq[row] = sq;
    __syncthreads();
    for (int i = tid; i < DIM; i += 256) atomicAdd(&g_colsum[i], cs[i]);
}

__global__ void bw_kernel() {
    __shared__ double sh[256];
    int t = threadIdx.x;
    double acc = 0.0;
    for (int i = t; i < N_TOT; i += 256) acc += (double)g_sq[i];
    double acc2 = 0.0;
    for (int i = t; i < DIM; i += 256) { double c = (double)g_colsum[i]; acc2 += c * c; }
    sh[t] = acc; __syncthreads();
    for (int o = 128; o; o >>= 1) { if (t < o) sh[t] += sh[t + o]; __syncthreads(); }
    double sumsq = sh[0];
    __syncthreads();
    sh[t] = acc2; __syncthreads();
    for (int o = 128; o; o >>= 1) { if (t < o) sh[t] += sh[t + o]; __syncthreads(); }
    if (t == 0) {
        double ss = sh[0];
        double sumL2 = 2.0 * (double)N_TOT * sumsq - 2.0 * ss;
        double bw = sumL2 / ((double)N_TOT * (double)N_TOT - (double)N_TOT);
        g_coef = (float)(-1.4426950408889634 / (4.0 * bw));
    }
}

// ---------------- tile index -> (ti, tj), tj >= ti ----------------
__device__ __forceinline__ void tile_coords(int tile, int& ti, int& tj) {
    int rem = tile, t = 0;
    while (rem >= GRID_T - t) { rem -= GRID_T - t; t++; }
    ti = t; tj = t + rem;
}

// ---------------- async tile loader (2 tiles: Ahi, Bhi) ----------------
__device__ __forceinline__ void load_chunk_async(uint32_t sbase, uint32_t stage, int c,
                                                 int rowA0, int rowB0, int tid) {
#pragma unroll
    for (int m = 0; m < 8; m++) {
        int u = tid + 256 * m;
        int t = u >> 10;            // 0: Ahi, 1: Bhi
        int v = u & 1023;
        int r = v >> 3;             // row 0..127
        int i16 = v & 7;            // 16B group within 128B row
        int grow = ((t == 0) ? rowA0 : rowB0) + r;
        const char* gp = (const char*)(g_hi + (size_t)grow * DIM) + c * 128 + i16 * 16;
        uint32_t dst = sbase + stage * SM_STAGE + (uint32_t)t * SM_TILE
                     + (uint32_t)(r * 128) + (uint32_t)((i16 ^ (r & 7)) << 4);
        asm volatile("cp.async.cg.shared.global [%0], [%1], 16;" :: "r"(dst), "l"(gp));
    }
}

// ------- persistent fused gram (bf16 HMMA) + RBF mixture, cross-tile pipe ----
__global__ __launch_bounds__(256, 2) void mmd_mma_kernel() {
    extern __shared__ char smem[];
    const uint32_t sbase = smem_u32_of(smem);
    int tid = threadIdx.x;
    int wid = tid >> 5, lane = tid & 31;

    int* ctrl = (int*)(smem + SM_CTRL);
    float* sqA_s = (float*)(smem + SM_SQA);
    float* sqB_s = (float*)(smem + SM_SQB);
    float* red = (float*)(smem + SM_RED);

    // warp tiling: 2 (rows) x 4 (cols) warps; warp tile 64x32
    int wr = wid >> 2, wc = wid & 3;
    int rA = wr * 64 + (lane & 15);
    int kgA = lane >> 4;
    int xrA = rA & 7;
    int nB = wc * 32 + (lane & 7) + ((lane >> 4) << 3);
    int kgB = (lane >> 3) & 1;
    int xrB = nB & 7;

    // fetch first tile
    if (tid == 0) ctrl[0] = atomicAdd(&g_tile_ctr, 1);
    __syncthreads();
    int cur = ctrl[0];
    if (cur >= NUM_TILES) return;
    int ti, tj;
    tile_coords(cur, ti, tj);
    int rowA0 = ti * TILE, rowB0 = tj * TILE;

    // prologue: chunks 0,1 of first tile -> stages 0,1
    load_chunk_async(sbase, 0, 0, rowA0, rowB0, tid);
    asm volatile("cp.async.commit_group;" ::: "memory");
    load_chunk_async(sbase, 1, 1, rowA0, rowB0, tid);
    asm volatile("cp.async.commit_group;" ::: "memory");

    int cstage = 0;      // stage holding current chunk's data
    float coef = g_coef;

    while (true) {
        float acc[4][4][4];
#pragma unroll
        for (int i = 0; i < 4; i++)
#pragma unroll
            for (int j = 0; j < 4; j++)
#pragma unroll
                for (int e = 0; e < 4; e++) acc[i][j][e] = 0.f;

        int next = NUM_TILES;   // valid after chunk 1
        for (int c = 0; c < NCHUNK; c++) {
            asm volatile("cp.async.wait_group 1;" ::: "memory");
            __syncthreads();
            // barrier proves compute of chunk c-1 done => stage (cstage+2)%3 free
            if (c == 0) {
                if (tid == 0) ctrl[0] = atomicAdd(&g_tile_ctr, 1);
                if (tid < 128) sqA_s[tid] = g_sq[rowA0 + tid];
                else           sqB_s[tid - 128] = g_sq[rowB0 + (tid - 128)];
            }
            if (c == 1) next = ctrl[0];

            int lstage = cstage + 2; if (lstage >= 3) lstage -= 3;
            int tgt = c + 2;
            if (tgt < NCHUNK) {
                load_chunk_async(sbase, (uint32_t)lstage, tgt, rowA0, rowB0, tid);
            } else if (next < NUM_TILES) {
                int nti, ntj;
                tile_coords(next, nti, ntj);
                load_chunk_async(sbase, (uint32_t)lstage, tgt - NCHUNK,
                                 nti * TILE, ntj * TILE, tid);
            }
            asm volatile("cp.async.commit_group;" ::: "memory");  // uniform accounting

            uint32_t stoff = (uint32_t)cstage * SM_STAGE;
            uint32_t aBase = sbase + stoff + (uint32_t)(rA * 128);
            uint32_t bBase = sbase + stoff + SM_TILE + (uint32_t)(nB * 128);
#pragma unroll
            for (int s = 0; s < 4; s++) {
                uint32_t colA = (uint32_t)(((s * 2 + kgA) ^ xrA) << 4);
                uint32_t colB = (uint32_t)(((s * 2 + kgB) ^ xrB) << 4);
                uint32_t ah[4][4], bh[2][4];
#pragma unroll
                for (int mi = 0; mi < 4; mi++)
                    LDSM_X4(ah[mi], aBase + (uint32_t)(mi * 16 * 128) + colA);
#pragma unroll
                for (int nb = 0; nb < 2; nb++)
                    LDSM_X4(bh[nb], bBase + (uint32_t)(nb * 16 * 128) + colB);
#pragma unroll
                for (int mi = 0; mi < 4; mi++) {
#pragma unroll
                    for (int ni = 0; ni < 4; ni++) {
                        int nb = ni >> 1, j = ni & 1;
                        MMA_BF16(acc[mi][ni], ah[mi], bh[nb][2 * j], bh[nb][2 * j + 1]);
                    }
                }
            }
            cstage++; if (cstage >= 3) cstage -= 3;
        }

        // ---------------- epilogue: RBF mixture ----------------
        float part = 0.f;
        int re = wr * 64 + (lane >> 2);
        int ce = wc * 32 + (lane & 3) * 2;
#pragma unroll
        for (int mi = 0; mi < 4; mi++) {
#pragma unroll
            for (int ni = 0; ni < 4; ni++) {
                int row = re + mi * 16;
                int col = ce + ni * 8;
#pragma unroll
                for (int e = 0; e < 4; e++) {
                    float sA = sqA_s[row + ((e >> 1) << 3)];
                    float sB = sqB_s[col + (e & 1)];
                    float L2 = sA + sB - 2.f * acc[mi][ni][e];
                    float t;
                    asm("ex2.approx.ftz.f32 %0, %1;" : "=f"(t) : "f"(L2 * coef));
                    float t2 = t * t, t4 = t2 * t2, t8 = t4 * t4, t16 = t8 * t8;
                    part += t + t2 + t4 + t8 + t16;
                }
            }
        }
#pragma unroll
        for (int o = 16; o; o >>= 1) part += __shfl_xor_sync(0xffffffffu, part, o);
        if (lane == 0) red[wid] = part;
        __syncthreads();
        if (wid == 0) {
            float v = (lane < 8) ? red[lane] : 0.f;
#pragma unroll
            for (int o = 4; o; o >>= 1) v += __shfl_xor_sync(0xffffffffu, v, o);
            if (lane == 0) {
                float sign = ((ti < GRID_T / 2) == (tj < GRID_T / 2)) ? 1.f : -1.f;
                float wgt = (ti == tj) ? 1.f : 2.f;
                g_partials[cur] = v * sign * wgt;
            }
        }

        if (next >= NUM_TILES) break;
        cur = next;
        tile_coords(cur, ti, tj);
        rowA0 = ti * TILE; rowB0 = tj * TILE;
    }
}

__global__ void reduce_kernel(float* __restrict__ out) {
    __shared__ double sh[256];
    int t = threadIdx.x;
    double a = 0.0;
    for (int i = t; i < NUM_TILES; i += 256) a += (double)g_partials[i];
    sh[t] = a; __syncthreads();
    for (int o = 128; o; o >>= 1) { if (t < o) sh[t] += sh[t + o]; __syncthreads(); }
    if (t == 0) out[0] = (float)(sh[0] / ((double)N_HALF * (double)N_HALF));
}

extern "C" void kernel_launch(void* const* d_in, const int* in_sizes, int n_in,
                              void* d_out, int out_size) {
    const float* src = (const float*)d_in[0];
    const float* tgt = (const float*)d_in[1];
    cudaFuncSetAttribute(mmd_mma_kernel, cudaFuncAttributeMaxDynamicSharedMemorySize,
                         SMEM_TOTAL);
    zero_colsum_kernel<<<2, 256>>>();
    prep_kernel<<<N_TOT / 8, 256>>>(src, tgt);
    bw_kernel<<<1, 256>>>();
    mmd_mma_kernel<<<NWORKERS, 256, SMEM_TOTAL>>>();
    reduce_kernel<<<1, 256>>>((float*)d_out);
}

// round 8
// speedup vs baseline: 1.0482x; 1.0482x over previous
#include <cuda_runtime.h>
#include <cuda_bf16.h>
#include <stdint.h>

#define N_HALF 4096
#define N_TOT  8192
#define DIM    512
#define TILE   128
#define NCHUNK 8
#define GRID_T 64
#define NUM_TILES 2080
#define PREP_CTAS (N_TOT / 8)

__device__ __nv_bfloat16 g_hi[(size_t)N_TOT * DIM];
__device__ float g_sq[N_TOT];
__device__ float g_colsum[DIM];          // statically zero-init; self-cleaned each run
__device__ float g_coef;
__device__ float g_partials[NUM_TILES];
__device__ int g_prep_done;              // self-cleaned
__device__ int g_mma_done;               // self-cleaned

__device__ __forceinline__ uint32_t smem_u32_of(const void* p) {
    uint32_t a;
    asm("{ .reg .u64 t; cvta.to.shared.u64 t, %1; cvt.u32.u64 %0, t; }" : "=r"(a) : "l"(p));
    return a;
}

#define LDSM_X4(r, addr)                                                       \
    asm volatile("ldmatrix.sync.aligned.m8n8.x4.shared.b16 {%0,%1,%2,%3}, [%4];" \
        : "=r"((r)[0]), "=r"((r)[1]), "=r"((r)[2]), "=r"((r)[3]) : "r"(addr))

#define MMA_BF16(c, a, b0, b1)                                                 \
    asm volatile("mma.sync.aligned.m16n8k16.row.col.f32.bf16.bf16.f32 "        \
        "{%0,%1,%2,%3},{%4,%5,%6,%7},{%8,%9},{%0,%1,%2,%3};"                   \
        : "+f"((c)[0]), "+f"((c)[1]), "+f"((c)[2]), "+f"((c)[3])               \
        : "r"((a)[0]), "r"((a)[1]), "r"((a)[2]), "r"((a)[3]), "r"(b0), "r"(b1))

// ---------------- smem map (bytes) ----------------
// per stage: Ahi (16K) | Bhi (16K) = 32K; 3 stages; 2 CTAs/SM
#define SM_TILE    16384
#define SM_STAGE   32768
#define SM_SQA     98304
#define SM_SQB     (SM_SQA + 512)
#define SM_RED     (SM_SQB + 512)
#define SM_CTRL    (SM_RED + 2048)
#define SMEM_TOTAL (SM_CTRL + 16)

// ------- prep: round to bf16, norms/colsums of ROUNDED data; last CTA -> bw ---
__global__ __launch_bounds__(256) void prep_kernel(const float* __restrict__ src,
                                                   const float* __restrict__ tgt) {
    __shared__ float cs[DIM];
    __shared__ int is_last;
    __shared__ double shd[256];
    int tid = threadIdx.x;
    for (int i = tid; i < DIM; i += 256) cs[i] = 0.f;
    __syncthreads();
    int warp = tid >> 5, lane = tid & 31;
    int row = blockIdx.x * 8 + warp;
    const float* p = (row < N_HALF) ? src + (size_t)row * DIM
                                    : tgt + (size_t)(row - N_HALF) * DIM;
    const float2* p2 = (const float2*)p;
    __nv_bfloat162* h2p = (__nv_bfloat162*)(g_hi + (size_t)row * DIM);
    float sq = 0.f;
#pragma unroll
    for (int i = 0; i < 8; i++) {
        int c = lane + 32 * i;
        float2 v = p2[c];
        __nv_bfloat16 hx = __float2bfloat16(v.x);
        __nv_bfloat16 hy = __float2bfloat16(v.y);
        float fx = __bfloat162float(hx);
        float fy = __bfloat162float(hy);
        sq += fx * fx + fy * fy;
        atomicAdd(&cs[2 * c], fx);
        atomicAdd(&cs[2 * c + 1], fy);
        __nv_bfloat162 h2; h2.x = hx; h2.y = hy;
        h2p[c] = h2;
    }
#pragma unroll
    for (int o = 16; o; o >>= 1) sq += __shfl_xor_sync(0xffffffffu, sq, o);
    if (lane == 0) g_sq[row] = sq;
    __syncthreads();
    for (int i = tid; i < DIM; i += 256) atomicAdd(&g_colsum[i], cs[i]);

    // ---- last-CTA-done: compute bandwidth coefficient ----
    if (tid == 0) {
        __threadfence();
        int d = atomicAdd(&g_prep_done, 1);
        is_last = (d == PREP_CTAS - 1);
    }
    __syncthreads();
    if (!is_last) return;
    __threadfence();

    double acc = 0.0;
    for (int i = tid; i < N_TOT; i += 256) acc += (double)g_sq[i];
    shd[tid] = acc; __syncthreads();
    for (int o = 128; o; o >>= 1) { if (tid < o) shd[tid] += shd[tid + o]; __syncthreads(); }
    double sumsq = shd[0];
    __syncthreads();
    double acc2 = 0.0;
    for (int i = tid; i < DIM; i += 256) { double c = (double)g_colsum[i]; acc2 += c * c; }
    shd[tid] = acc2; __syncthreads();
    for (int o = 128; o; o >>= 1) { if (tid < o) shd[tid] += shd[tid + o]; __syncthreads(); }
    if (tid == 0) {
        double ss = shd[0];
        double sumL2 = 2.0 * (double)N_TOT * sumsq - 2.0 * ss;
        double bw = sumL2 / ((double)N_TOT * (double)N_TOT - (double)N_TOT);
        g_coef = (float)(-1.4426950408889634 / (4.0 * bw));
        g_prep_done = 0;                   // self-clean for next replay
    }
    for (int i = tid; i < DIM; i += 256) g_colsum[i] = 0.f;   // self-clean
}

// ---------------- async tile loader (2 tiles: Ahi, Bhi) ----------------
__device__ __forceinline__ void load_chunk_async(uint32_t sbase, uint32_t stage, int c,
                                                 int rowA0, int rowB0, int tid) {
#pragma unroll
    for (int m = 0; m < 8; m++) {
        int u = tid + 256 * m;
        int t = u >> 10;            // 0: Ahi, 1: Bhi
        int v = u & 1023;
        int r = v >> 3;             // row 0..127
        int i16 = v & 7;            // 16B group within 128B row
        int grow = ((t == 0) ? rowA0 : rowB0) + r;
        const char* gp = (const char*)(g_hi + (size_t)grow * DIM) + c * 128 + i16 * 16;
        uint32_t dst = sbase + stage * SM_STAGE + (uint32_t)t * SM_TILE
                     + (uint32_t)(r * 128) + (uint32_t)((i16 ^ (r & 7)) << 4);
        asm volatile("cp.async.cg.shared.global [%0], [%1], 16;" :: "r"(dst), "l"(gp));
    }
}

// ---- fused gram (single-product bf16 HMMA) + RBF mixture; last CTA reduces ---
__global__ __launch_bounds__(256, 2) void mmd_mma_kernel(float* __restrict__ out) {
    extern __shared__ char smem[];
    const uint32_t sbase = smem_u32_of(smem);
    int tid = threadIdx.x;
    int wid = tid >> 5, lane = tid & 31;

    int rem = blockIdx.x, ti = 0;
    while (rem >= GRID_T - ti) { rem -= GRID_T - ti; ti++; }
    int tj = ti + rem;
    int rowA0 = ti * TILE, rowB0 = tj * TILE;

    float* sqA_s = (float*)(smem + SM_SQA);
    float* sqB_s = (float*)(smem + SM_SQB);
    if (tid < 128) sqA_s[tid] = g_sq[rowA0 + tid];
    else           sqB_s[tid - 128] = g_sq[rowB0 + (tid - 128)];

    // prologue: chunks 0,1 -> stages 0,1
    load_chunk_async(sbase, 0, 0, rowA0, rowB0, tid);
    asm volatile("cp.async.commit_group;" ::: "memory");
    load_chunk_async(sbase, 1, 1, rowA0, rowB0, tid);
    asm volatile("cp.async.commit_group;" ::: "memory");

    // warp tiling: 2 (rows) x 4 (cols) warps; warp tile 64x32
    int wr = wid >> 2, wc = wid & 3;
    int rA = wr * 64 + (lane & 15);
    int kgA = lane >> 4;
    int xrA = rA & 7;
    uint32_t aAddr[4];
#pragma unroll
    for (int mi = 0; mi < 4; mi++)
        aAddr[mi] = sbase + (uint32_t)((rA + mi * 16) * 128);
    int nB = wc * 32 + (lane & 7) + ((lane >> 4) << 3);
    int kgB = (lane >> 3) & 1;
    int xrB = nB & 7;
    uint32_t bAddr[2];
#pragma unroll
    for (int nb = 0; nb < 2; nb++)
        bAddr[nb] = sbase + SM_TILE + (uint32_t)((nB + nb * 16) * 128);

    float acc[4][4][4];
#pragma unroll
    for (int i = 0; i < 4; i++)
#pragma unroll
        for (int j = 0; j < 4; j++)
#pragma unroll
            for (int e = 0; e < 4; e++) acc[i][j][e] = 0.f;

    int stage = 0;
    for (int c = 0; c < NCHUNK; c++) {
        if (c + 1 < NCHUNK) asm volatile("cp.async.wait_group 1;" ::: "memory");
        else                asm volatile("cp.async.wait_group 0;" ::: "memory");
        __syncthreads();
        // barrier proves compute of chunk c-1 done => its stage (= (c+2)%3) is free
        if (c + 2 < NCHUNK) {
            int sn = stage + 2; if (sn >= 3) sn -= 3;
            load_chunk_async(sbase, (uint32_t)sn, c + 2, rowA0, rowB0, tid);
            asm volatile("cp.async.commit_group;" ::: "memory");
        }
        uint32_t stoff = (uint32_t)stage * SM_STAGE;
#pragma unroll
        for (int s = 0; s < 4; s++) {
            uint32_t colA = (uint32_t)(((s * 2 + kgA) ^ xrA) << 4);
            uint32_t colB = (uint32_t)(((s * 2 + kgB) ^ xrB) << 4);
            uint32_t ah[4][4], bh[2][4];
#pragma unroll
            for (int mi = 0; mi < 4; mi++)
                LDSM_X4(ah[mi], aAddr[mi] + stoff + colA);
#pragma unroll
            for (int nb = 0; nb < 2; nb++)
                LDSM_X4(bh[nb], bAddr[nb] + stoff + colB);
#pragma unroll
            for (int mi = 0; mi < 4; mi++) {
#pragma unroll
                for (int ni = 0; ni < 4; ni++) {
                    int nb = ni >> 1, j = ni & 1;
                    MMA_BF16(acc[mi][ni], ah[mi], bh[nb][2 * j], bh[nb][2 * j + 1]);
                }
            }
        }
        stage++; if (stage >= 3) stage = 0;
    }

    // epilogue: RBF mixture from register accumulators
    float coef = g_coef;
    float part = 0.f;
    int re = wr * 64 + (lane >> 2);
    int ce = wc * 32 + (lane & 3) * 2;
#pragma unroll
    for (int mi = 0; mi < 4; mi++) {
#pragma unroll
        for (int ni = 0; ni < 4; ni++) {
            int row = re + mi * 16;
            int col = ce + ni * 8;
#pragma unroll
            for (int e = 0; e < 4; e++) {
                float sA = sqA_s[row + ((e >> 1) << 3)];
                float sB = sqB_s[col + (e & 1)];
                float L2 = sA + sB - 2.f * acc[mi][ni][e];
                float t;
                asm("ex2.approx.ftz.f32 %0, %1;" : "=f"(t) : "f"(L2 * coef));
                float t2 = t * t, t4 = t2 * t2, t8 = t4 * t4, t16 = t8 * t8;
                part += t + t2 + t4 + t8 + t16;
            }
        }
    }

    float* red = (float*)(smem + SM_RED);
#pragma unroll
    for (int o = 16; o; o >>= 1) part += __shfl_xor_sync(0xffffffffu, part, o);
    if (lane == 0) red[wid] = part;
    __syncthreads();
    if (wid == 0) {
        float v = (lane < 8) ? red[lane] : 0.f;
#pragma unroll
        for (int o = 4; o; o >>= 1) v += __shfl_xor_sync(0xffffffffu, v, o);
        if (lane == 0) {
            float sign = ((ti < GRID_T / 2) == (tj < GRID_T / 2)) ? 1.f : -1.f;
            float wgt = (ti == tj) ? 1.f : 2.f;
            g_partials[blockIdx.x] = v * sign * wgt;
        }
    }

    // ---- last-CTA-done: final reduction (cold path) ----
    int* is_last = (int*)(smem + SM_CTRL);
    if (tid == 0) {
        __threadfence();
        int d = atomicAdd(&g_mma_done, 1);
        *is_last = (d == NUM_TILES - 1);
    }
    __syncthreads();
    if (!*is_last) return;
    __threadfence();

    double* shd = (double*)(smem + SM_RED);
    double a = 0.0;
    for (int i = tid; i < NUM_TILES; i += 256) a += (double)g_partials[i];
    shd[tid] = a; __syncthreads();
    for (int o = 128; o; o >>= 1) { if (tid < o) shd[tid] += shd[tid + o]; __syncthreads(); }
    if (tid == 0) {
        out[0] = (float)(shd[0] / ((double)N_HALF * (double)N_HALF));
        g_mma_done = 0;                    // self-clean for next replay
    }
}

extern "C" void kernel_launch(void* const* d_in, const int* in_sizes, int n_in,
                              void* d_out, int out_size) {
    const float* src = (const float*)d_in[0];
    const float* tgt = (const float*)d_in[1];
    cudaFuncSetAttribute(mmd_mma_kernel, cudaFuncAttributeMaxDynamicSharedMemorySize,
                         SMEM_TOTAL);
    prep_kernel<<<PREP_CTAS, 256>>>(src, tgt);
    mmd_mma_kernel<<<NUM_TILES, 256, SMEM_TOTAL>>>((float*)d_out);
}

// round 9
// speedup vs baseline: 1.0634x; 1.0145x over previous
#include <cuda_runtime.h>
#include <cuda_bf16.h>
#include <stdint.h>

#define N_HALF 4096
#define N_TOT  8192
#define DIM    512
#define TILE   128
#define NCHUNK 8
#define GRID_T 64
#define NUM_TILES 2080
#define PREP_CTAS (N_TOT / 8)

__device__ __nv_bfloat16 g_hi[(size_t)N_TOT * DIM];
__device__ float g_sq[N_TOT];
__device__ float g_colsum[DIM];          // statically zero-init; self-cleaned each run
__device__ float g_coef;
__device__ float g_partials[NUM_TILES];
__device__ int g_prep_done;              // self-cleaned

__device__ __forceinline__ uint32_t smem_u32_of(const void* p) {
    uint32_t a;
    asm("{ .reg .u64 t; cvta.to.shared.u64 t, %1; cvt.u32.u64 %0, t; }" : "=r"(a) : "l"(p));
    return a;
}

#define LDSM_X4(r, addr)                                                       \
    asm volatile("ldmatrix.sync.aligned.m8n8.x4.shared.b16 {%0,%1,%2,%3}, [%4];" \
        : "=r"((r)[0]), "=r"((r)[1]), "=r"((r)[2]), "=r"((r)[3]) : "r"(addr))

#define MMA_BF16(c, a, b0, b1)                                                 \
    asm volatile("mma.sync.aligned.m16n8k16.row.col.f32.bf16.bf16.f32 "        \
        "{%0,%1,%2,%3},{%4,%5,%6,%7},{%8,%9},{%0,%1,%2,%3};"                   \
        : "+f"((c)[0]), "+f"((c)[1]), "+f"((c)[2]), "+f"((c)[3])               \
        : "r"((a)[0]), "r"((a)[1]), "r"((a)[2]), "r"((a)[3]), "r"(b0), "r"(b1))

// ---------------- smem map (bytes) ----------------
// per stage: Ahi (16K) | Bhi (16K) = 32K; 3 stages; 2 CTAs/SM
#define SM_TILE    16384
#define SM_STAGE   32768
#define SM_SQA     98304
#define SM_SQB     (SM_SQA + 512)
#define SM_RED     (SM_SQB + 512)
#define SMEM_TOTAL (SM_RED + 1024)

// ------- prep: round to bf16, norms/colsums of ROUNDED data; last CTA -> bw ---
__global__ __launch_bounds__(256) void prep_kernel(const float* __restrict__ src,
                                                   const float* __restrict__ tgt) {
    __shared__ float cs[DIM];
    __shared__ int is_last;
    __shared__ double shd[256];
    int tid = threadIdx.x;
    for (int i = tid; i < DIM; i += 256) cs[i] = 0.f;
    __syncthreads();
    int warp = tid >> 5, lane = tid & 31;
    int row = blockIdx.x * 8 + warp;
    const float* p = (row < N_HALF) ? src + (size_t)row * DIM
                                    : tgt + (size_t)(row - N_HALF) * DIM;
    const float2* p2 = (const float2*)p;
    __nv_bfloat162* h2p = (__nv_bfloat162*)(g_hi + (size_t)row * DIM);
    float sq = 0.f;
#pragma unroll
    for (int i = 0; i < 8; i++) {
        int c = lane + 32 * i;
        float2 v = p2[c];
        __nv_bfloat16 hx = __float2bfloat16(v.x);
        __nv_bfloat16 hy = __float2bfloat16(v.y);
        float fx = __bfloat162float(hx);
        float fy = __bfloat162float(hy);
        sq += fx * fx + fy * fy;
        atomicAdd(&cs[2 * c], fx);
        atomicAdd(&cs[2 * c + 1], fy);
        __nv_bfloat162 h2; h2.x = hx; h2.y = hy;
        h2p[c] = h2;
    }
#pragma unroll
    for (int o = 16; o; o >>= 1) sq += __shfl_xor_sync(0xffffffffu, sq, o);
    if (lane == 0) g_sq[row] = sq;
    __syncthreads();
    for (int i = tid; i < DIM; i += 256) atomicAdd(&g_colsum[i], cs[i]);

    // ---- last-CTA-done: compute bandwidth coefficient ----
    if (tid == 0) {
        __threadfence();
        int d = atomicAdd(&g_prep_done, 1);
        is_last = (d == PREP_CTAS - 1);
    }
    __syncthreads();
    if (!is_last) return;
    __threadfence();

    double acc = 0.0;
    for (int i = tid; i < N_TOT; i += 256) acc += (double)g_sq[i];
    shd[tid] = acc; __syncthreads();
    for (int o = 128; o; o >>= 1) { if (tid < o) shd[tid] += shd[tid + o]; __syncthreads(); }
    double sumsq = shd[0];
    __syncthreads();
    double acc2 = 0.0;
    for (int i = tid; i < DIM; i += 256) { double c = (double)g_colsum[i]; acc2 += c * c; }
    shd[tid] = acc2; __syncthreads();
    for (int o = 128; o; o >>= 1) { if (tid < o) shd[tid] += shd[tid + o]; __syncthreads(); }
    if (tid == 0) {
        double ss = shd[0];
        double sumL2 = 2.0 * (double)N_TOT * sumsq - 2.0 * ss;
        double bw = sumL2 / ((double)N_TOT * (double)N_TOT - (double)N_TOT);
        g_coef = (float)(-1.4426950408889634 / (4.0 * bw));
        g_prep_done = 0;                   // self-clean for next replay
    }
    for (int i = tid; i < DIM; i += 256) g_colsum[i] = 0.f;   // self-clean
}

// ---------------- async tile loader (2 tiles: Ahi, Bhi) ----------------
__device__ __forceinline__ void load_chunk_async(uint32_t sbase, uint32_t stage, int c,
                                                 int rowA0, int rowB0, int tid) {
#pragma unroll
    for (int m = 0; m < 8; m++) {
        int u = tid + 256 * m;
        int t = u >> 10;            // 0: Ahi, 1: Bhi
        int v = u & 1023;
        int r = v >> 3;             // row 0..127
        int i16 = v & 7;            // 16B group within 128B row
        int grow = ((t == 0) ? rowA0 : rowB0) + r;
        const char* gp = (const char*)(g_hi + (size_t)grow * DIM) + c * 128 + i16 * 16;
        uint32_t dst = sbase + stage * SM_STAGE + (uint32_t)t * SM_TILE
                     + (uint32_t)(r * 128) + (uint32_t)((i16 ^ (r & 7)) << 4);
        asm volatile("cp.async.cg.shared.global [%0], [%1], 16;" :: "r"(dst), "l"(gp));
    }
}

// ---------------- fused gram (single-product bf16 HMMA) + RBF mixture --------
__global__ __launch_bounds__(256, 2) void mmd_mma_kernel() {
    extern __shared__ char smem[];
    const uint32_t sbase = smem_u32_of(smem);
    int tid = threadIdx.x;
    int wid = tid >> 5, lane = tid & 31;

    int rem = blockIdx.x, ti = 0;
    while (rem >= GRID_T - ti) { rem -= GRID_T - ti; ti++; }
    int tj = ti + rem;
    int rowA0 = ti * TILE, rowB0 = tj * TILE;

    float* sqA_s = (float*)(smem + SM_SQA);
    float* sqB_s = (float*)(smem + SM_SQB);
    if (tid < 128) sqA_s[tid] = g_sq[rowA0 + tid];
    else           sqB_s[tid - 128] = g_sq[rowB0 + (tid - 128)];

    // prologue: chunks 0,1 -> stages 0,1
    load_chunk_async(sbase, 0, 0, rowA0, rowB0, tid);
    asm volatile("cp.async.commit_group;" ::: "memory");
    load_chunk_async(sbase, 1, 1, rowA0, rowB0, tid);
    asm volatile("cp.async.commit_group;" ::: "memory");

    // warp tiling: 2 (rows) x 4 (cols) warps; warp tile 64x32
    int wr = wid >> 2, wc = wid & 3;
    int rA = wr * 64 + (lane & 15);
    int kgA = lane >> 4;
    int xrA = rA & 7;
    uint32_t aAddr[4];
#pragma unroll
    for (int mi = 0; mi < 4; mi++)
        aAddr[mi] = sbase + (uint32_t)((rA + mi * 16) * 128);
    int nB = wc * 32 + (lane & 7) + ((lane >> 4) << 3);
    int kgB = (lane >> 3) & 1;
    int xrB = nB & 7;
    uint32_t bAddr[2];
#pragma unroll
    for (int nb = 0; nb < 2; nb++)
        bAddr[nb] = sbase + SM_TILE + (uint32_t)((nB + nb * 16) * 128);

    float acc[4][4][4];
#pragma unroll
    for (int i = 0; i < 4; i++)
#pragma unroll
        for (int j = 0; j < 4; j++)
#pragma unroll
            for (int e = 0; e < 4; e++) acc[i][j][e] = 0.f;

    int stage = 0;
    for (int c = 0; c < NCHUNK; c++) {
        if (c + 1 < NCHUNK) asm volatile("cp.async.wait_group 1;" ::: "memory");
        else                asm volatile("cp.async.wait_group 0;" ::: "memory");
        __syncthreads();
        // barrier proves compute of chunk c-1 done => its stage (= (c+2)%3) is free
        if (c + 2 < NCHUNK) {
            int sn = stage + 2; if (sn >= 3) sn -= 3;
            load_chunk_async(sbase, (uint32_t)sn, c + 2, rowA0, rowB0, tid);
            asm volatile("cp.async.commit_group;" ::: "memory");
        }
        uint32_t stoff = (uint32_t)stage * SM_STAGE;
#pragma unroll
        for (int s = 0; s < 4; s++) {
            uint32_t colA = (uint32_t)(((s * 2 + kgA) ^ xrA) << 4);
            uint32_t colB = (uint32_t)(((s * 2 + kgB) ^ xrB) << 4);
            uint32_t ah[4][4], bh[2][4];
#pragma unroll
            for (int mi = 0; mi < 4; mi++)
                LDSM_X4(ah[mi], aAddr[mi] + stoff + colA);
#pragma unroll
            for (int nb = 0; nb < 2; nb++)
                LDSM_X4(bh[nb], bAddr[nb] + stoff + colB);
#pragma unroll
            for (int mi = 0; mi < 4; mi++) {
#pragma unroll
                for (int ni = 0; ni < 4; ni++) {
                    int nb = ni >> 1, j = ni & 1;
                    MMA_BF16(acc[mi][ni], ah[mi], bh[nb][2 * j], bh[nb][2 * j + 1]);
                }
            }
        }
        stage++; if (stage >= 3) stage = 0;
    }

    // epilogue: RBF mixture from register accumulators
    float coef = g_coef;
    float part = 0.f;
    int re = wr * 64 + (lane >> 2);
    int ce = wc * 32 + (lane & 3) * 2;
#pragma unroll
    for (int mi = 0; mi < 4; mi++) {
#pragma unroll
        for (int ni = 0; ni < 4; ni++) {
            int row = re + mi * 16;
            int col = ce + ni * 8;
#pragma unroll
            for (int e = 0; e < 4; e++) {
                float sA = sqA_s[row + ((e >> 1) << 3)];
                float sB = sqB_s[col + (e & 1)];
                float L2 = sA + sB - 2.f * acc[mi][ni][e];
                float t;
                asm("ex2.approx.ftz.f32 %0, %1;" : "=f"(t) : "f"(L2 * coef));
                float t2 = t * t, t4 = t2 * t2, t8 = t4 * t4, t16 = t8 * t8;
                part += t + t2 + t4 + t8 + t16;
            }
        }
    }

    float* red = (float*)(smem + SM_RED);
    red[tid] = part;
    __syncthreads();
#pragma unroll
    for (int o = 128; o; o >>= 1) {
        if (tid < o) red[tid] += red[tid + o];
        __syncthreads();
    }
    if (tid == 0) {
        float sign = ((ti < GRID_T / 2) == (tj < GRID_T / 2)) ? 1.f : -1.f;
        float wgt = (ti == tj) ? 1.f : 2.f;
        g_partials[blockIdx.x] = red[0] * sign * wgt;
    }
}

__global__ void reduce_kernel(float* __restrict__ out) {
    __shared__ double sh[64];
    int t = threadIdx.x;
    double a = 0.0;
    for (int i = t; i < NUM_TILES; i += 64) a += (double)g_partials[i];
    sh[t] = a; __syncthreads();
    for (int o = 32; o; o >>= 1) { if (t < o) sh[t] += sh[t + o]; __syncthreads(); }
    if (t == 0) out[0] = (float)(sh[0] / ((double)N_HALF * (double)N_HALF));
}

extern "C" void kernel_launch(void* const* d_in, const int* in_sizes, int n_in,
                              void* d_out, int out_size) {
    const float* src = (const float*)d_in[0];
    const float* tgt = (const float*)d_in[1];
    cudaFuncSetAttribute(mmd_mma_kernel, cudaFuncAttributeMaxDynamicSharedMemorySize,
                         SMEM_TOTAL);
    prep_kernel<<<PREP_CTAS, 256>>>(src, tgt);
    mmd_mma_kernel<<<NUM_TILES, 256, SMEM_TOTAL>>>();
    reduce_kernel<<<1, 64>>>((float*)d_out);
}